// round 2
// baseline (speedup 1.0000x reference)
#include <cuda_runtime.h>
#include <cstdint>

#define NN 8192
#define BLOCK 256
#define NBLK 296                      // 2 CTAs x 148 SMs, balanced row split
#define HALF (NN / 2)                 // 4096 columns per half-pass
#define HCHUNKS (HALF / (BLOCK * 4))  // 4 float4 chunks per thread per half
#define NWARP (BLOCK / 32)

// scratch (allocation-free rule: __device__ globals)
__device__ float g_p0[NN], g_p1[NN], g_p2[NN];
__device__ float g_deg[NN];
__device__ float g_dot[NN * 3];
__device__ int   g_done;

// ---- packed f32x2 helpers (sm_100 native) ----
__device__ __forceinline__ uint64_t ffma2(uint64_t a, uint64_t b, uint64_t c) {
    uint64_t d;
    asm("fma.rn.f32x2 %0, %1, %2, %3;" : "=l"(d) : "l"(a), "l"(b), "l"(c));
    return d;
}
__device__ __forceinline__ uint64_t fadd2(uint64_t a, uint64_t b) {
    uint64_t d;
    asm("add.rn.f32x2 %0, %1, %2;" : "=l"(d) : "l"(a), "l"(b));
    return d;
}
__device__ __forceinline__ void unpack2(uint64_t a, float& lo, float& hi) {
    uint32_t l, h;
    asm("mov.b64 {%0,%1}, %2;" : "=r"(l), "=r"(h) : "l"(a));
    lo = __uint_as_float(l);
    hi = __uint_as_float(h);
}
__device__ __forceinline__ float hadd2(uint64_t a) {
    float lo, hi;
    unpack2(a, lo, hi);
    return lo + hi;
}

__global__ void prep_kernel(const float* __restrict__ pred1,
                            const float* __restrict__ pred2) {
    int i = blockIdx.x * blockDim.x + threadIdx.x;
    if (i < NN) {
        g_p0[i] = pred2[3 * i + 0] - pred1[3 * i + 0];
        g_p1[i] = pred2[3 * i + 1] - pred1[3 * i + 1];
        g_p2[i] = pred2[3 * i + 2] - pred1[3 * i + 2];
        g_deg[i] = 0.0f;
        g_dot[3 * i + 0] = 0.0f;
        g_dot[3 * i + 1] = 0.0f;
        g_dot[3 * i + 2] = 0.0f;
        if (i == 0) g_done = 0;
    }
}

// Process R consecutive rows over one column half. Packed f32x2 math:
// per 16B of A (one LDG.128 -> two packed pairs): 6 ffma2 (D=3 dots) + 2 fadd2 (deg).
template <int R>
__device__ __forceinline__ void process_rows(
    const float* __restrict__ A, int row0, int colbase,
    const float* sp0, const float* sp1, const float* sp2,
    float* red, uint64_t* deg2, int tid, int lane, int warp) {

    uint64_t acc[R][3][2];
    #pragma unroll
    for (int r = 0; r < R; r++)
        #pragma unroll
        for (int d = 0; d < 3; d++) {
            acc[r][d][0] = 0ull;
            acc[r][d][1] = 0ull;
        }

    #pragma unroll
    for (int c = 0; c < HCHUNKS; c++) {
        const int col = colbase + (c * BLOCK + tid) * 4;
        const ulonglong2 pa = *reinterpret_cast<const ulonglong2*>(sp0 + col);
        const ulonglong2 pb = *reinterpret_cast<const ulonglong2*>(sp1 + col);
        const ulonglong2 pc = *reinterpret_cast<const ulonglong2*>(sp2 + col);

        #pragma unroll
        for (int r = 0; r < R; r++) {
            const ulonglong2 av = *reinterpret_cast<const ulonglong2*>(
                A + (size_t)(row0 + r) * NN + col);
            acc[r][0][0] = ffma2(av.x, pa.x, acc[r][0][0]);
            acc[r][0][1] = ffma2(av.y, pa.y, acc[r][0][1]);
            acc[r][1][0] = ffma2(av.x, pb.x, acc[r][1][0]);
            acc[r][1][1] = ffma2(av.y, pb.y, acc[r][1][1]);
            acc[r][2][0] = ffma2(av.x, pc.x, acc[r][2][0]);
            acc[r][2][1] = ffma2(av.y, pc.y, acc[r][2][1]);
            deg2[c * 2 + 0] = fadd2(deg2[c * 2 + 0], av.x);
            deg2[c * 2 + 1] = fadd2(deg2[c * 2 + 1], av.y);
        }
    }

    // block-reduce the R*3 row partials
    #pragma unroll
    for (int r = 0; r < R; r++)
        #pragma unroll
        for (int d = 0; d < 3; d++) {
            float v = hadd2(acc[r][d][0]) + hadd2(acc[r][d][1]);
            v += __shfl_down_sync(0xFFFFFFFFu, v, 16);
            v += __shfl_down_sync(0xFFFFFFFFu, v, 8);
            v += __shfl_down_sync(0xFFFFFFFFu, v, 4);
            v += __shfl_down_sync(0xFFFFFFFFu, v, 2);
            v += __shfl_down_sync(0xFFFFFFFFu, v, 1);
            if (lane == 0) red[warp * (R * 3) + r * 3 + d] = v;
        }
    __syncthreads();
    if (tid < R * 3) {
        float v = 0.0f;
        #pragma unroll
        for (int w = 0; w < NWARP; w++) v += red[w * (R * 3) + tid];
        const int r = tid / 3;
        const int d = tid - r * 3;
        atomicAdd(&g_dot[(row0 + r) * 3 + d], v);
    }
    __syncthreads();
}

__global__ __launch_bounds__(BLOCK, 2)
void spmm_kernel(const float* __restrict__ A, float* __restrict__ out) {
    extern __shared__ float smem[];
    float* sp0 = smem;
    float* sp1 = smem + NN;
    float* sp2 = smem + 2 * NN;
    float* red = smem + 3 * NN;   // NWARP * 12 floats

    const int tid  = threadIdx.x;
    const int lane = tid & 31;
    const int warp = tid >> 5;

    // stage p into smem (SoA, vectorized)
    {
        const float4* s0 = reinterpret_cast<const float4*>(g_p0);
        const float4* s1 = reinterpret_cast<const float4*>(g_p1);
        const float4* s2 = reinterpret_cast<const float4*>(g_p2);
        float4* d0 = reinterpret_cast<float4*>(sp0);
        float4* d1 = reinterpret_cast<float4*>(sp1);
        float4* d2 = reinterpret_cast<float4*>(sp2);
        for (int i = tid; i < NN / 4; i += BLOCK) {
            d0[i] = s0[i];
            d1[i] = s1[i];
            d2[i] = s2[i];
        }
    }
    __syncthreads();

    const int row_begin = (int)(((long)blockIdx.x * NN) / NBLK);
    const int row_end   = (int)(((long)(blockIdx.x + 1) * NN) / NBLK);

    for (int h = 0; h < 2; h++) {
        const int colbase = h * HALF;

        uint64_t deg2[HCHUNKS * 2];
        #pragma unroll
        for (int i = 0; i < HCHUNKS * 2; i++) deg2[i] = 0ull;

        int rg = row_begin;
        for (; rg + 4 <= row_end; rg += 4)
            process_rows<4>(A, rg, colbase, sp0, sp1, sp2, red, deg2, tid, lane, warp);
        for (; rg + 2 <= row_end; rg += 2)
            process_rows<2>(A, rg, colbase, sp0, sp1, sp2, red, deg2, tid, lane, warp);
        for (; rg < row_end; rg++)
            process_rows<1>(A, rg, colbase, sp0, sp1, sp2, red, deg2, tid, lane, warp);

        // flush column-sum partials (each thread owns distinct columns -> spread atomics)
        #pragma unroll
        for (int c = 0; c < HCHUNKS; c++) {
            const int col = colbase + (c * BLOCK + tid) * 4;
            float a, b;
            unpack2(deg2[c * 2 + 0], a, b);
            atomicAdd(&g_deg[col + 0], a);
            atomicAdd(&g_deg[col + 1], b);
            unpack2(deg2[c * 2 + 1], a, b);
            atomicAdd(&g_deg[col + 2], a);
            atomicAdd(&g_deg[col + 3], b);
        }
    }

    // ---- fused loss: last block to finish computes the scalar ----
    __shared__ int isLast;
    __syncthreads();
    if (tid == 0) {
        __threadfence();
        const int d = atomicAdd(&g_done, 1);
        isLast = (d == NBLK - 1);
    }
    __syncthreads();

    if (isLast) {
        __threadfence();
        float s = 0.0f;
        for (int i = tid; i < NN; i += BLOCK) {
            const float inv = 1.0f / __ldcg(&g_deg[i]);
            const float d0 = sp0[i] - __ldcg(&g_dot[3 * i + 0]) * inv;
            const float d1 = sp1[i] - __ldcg(&g_dot[3 * i + 1]) * inv;
            const float d2 = sp2[i] - __ldcg(&g_dot[3 * i + 2]) * inv;
            s += d0 * d0 + d1 * d1 + d2 * d2;
        }
        s += __shfl_down_sync(0xFFFFFFFFu, s, 16);
        s += __shfl_down_sync(0xFFFFFFFFu, s, 8);
        s += __shfl_down_sync(0xFFFFFFFFu, s, 4);
        s += __shfl_down_sync(0xFFFFFFFFu, s, 2);
        s += __shfl_down_sync(0xFFFFFFFFu, s, 1);
        if (lane == 0) red[warp] = s;
        __syncthreads();
        if (tid == 0) {
            float v = 0.0f;
            #pragma unroll
            for (int w = 0; w < NWARP; w++) v += red[w];
            out[0] = v;
        }
    }
}

extern "C" void kernel_launch(void* const* d_in, const int* in_sizes, int n_in,
                              void* d_out, int out_size) {
    const float* pred1 = (const float*)d_in[0];
    const float* pred2 = (const float*)d_in[1];
    const float* A     = (const float*)d_in[2];
    float* out = (float*)d_out;

    const int smem_bytes = (3 * NN + 12 * NWARP) * (int)sizeof(float);
    cudaFuncSetAttribute(spmm_kernel,
                         cudaFuncAttributeMaxDynamicSharedMemorySize, smem_bytes);

    prep_kernel<<<(NN + 255) / 256, 256>>>(pred1, pred2);
    spmm_kernel<<<NBLK, BLOCK, smem_bytes>>>(A, out);
}